// round 14
// baseline (speedup 1.0000x reference)
#include <cuda_runtime.h>
#include <stdint.h>
#include <stddef.h>

// SNG pipeline, closed form: the reference's sequential scan over T cycles
// collapses (module 0's pipeline input is hard-wired 0) to
//   sn[b,l] = maj-chain over the anti-diagonal r[b, i, l+i], i = 0..P-1,
//   seeded a = x_0 & r[b,0,l];  a <- maj(x_i, a, r[b,i,l+i]).
// Output dtype float32 (confirmed R6). Bitwise maj over RAW words with
// masks m_i = -bit_i keeps the accumulator in {0, V}; one (a != 0)/output.
//
// TERMINAL: x4/256/plain-stores. Best total 88.35us, best kernel 85.5us,
// DRAM 88.0%, 6.97 TB/s. DRAM bytes == theoretical minimum (596 MB) ==
// B300 practical memory ceiling. x8, __stcs, and 512-thread blocks each
// tested across R7-R13: neutral-to-worse. Holding the optimum.

#define MAJ(a, m, w) (((a) & (w)) | ((m) & ((a) | (w))))

__device__ __forceinline__ int decode_num(unsigned nw) {
    if (nw == 0u)             return 0;
    if (nw < (1u << 24))      return (int)nw;               // int32 storage
    return (int)__uint_as_float(nw);                        // float32 storage
}

__global__ __launch_bounds__(256)
void sng_p8x4(const unsigned* __restrict__ num,
              const unsigned* __restrict__ r,
              float* __restrict__ out,
              int L4, int T)
{
    const int q = blockIdx.x * 256 + threadIdx.x;
    if (q >= L4) return;
    const int l0 = q << 2;
    const int b  = blockIdx.y;

    const unsigned* rb = r + (size_t)b * (8ULL * (size_t)T);

    // Front-batched 128-bit loads (anti-diagonal, statically selected).
    const uint4 A0 = *(const uint4*)(rb + 0 * T + l0);
    const uint4 A1 = *(const uint4*)(rb + 1 * T + l0);
    const uint4 B1 = *(const uint4*)(rb + 1 * T + l0 + 4);
    const uint4 A2 = *(const uint4*)(rb + 2 * T + l0);
    const uint4 B2 = *(const uint4*)(rb + 2 * T + l0 + 4);
    const uint4 A3 = *(const uint4*)(rb + 3 * T + l0);
    const uint4 B3 = *(const uint4*)(rb + 3 * T + l0 + 4);
    const uint4 A4 = *(const uint4*)(rb + 4 * T + l0 + 4);
    const uint4 A5 = *(const uint4*)(rb + 5 * T + l0 + 4);
    const uint4 B5 = *(const uint4*)(rb + 5 * T + l0 + 8);
    const uint4 A6 = *(const uint4*)(rb + 6 * T + l0 + 4);
    const uint4 B6 = *(const uint4*)(rb + 6 * T + l0 + 8);
    const uint4 A7 = *(const uint4*)(rb + 7 * T + l0 + 4);
    const uint4 B7 = *(const uint4*)(rb + 7 * T + l0 + 8);

    const int x = decode_num(__ldg(num + b));
    const unsigned m0 = (unsigned)-( x       & 1);
    const unsigned m1 = (unsigned)-((x >> 1) & 1);
    const unsigned m2 = (unsigned)-((x >> 2) & 1);
    const unsigned m3 = (unsigned)-((x >> 3) & 1);
    const unsigned m4 = (unsigned)-((x >> 4) & 1);
    const unsigned m5 = (unsigned)-((x >> 5) & 1);
    const unsigned m6 = (unsigned)-((x >> 6) & 1);
    const unsigned m7 = (unsigned)-((x >> 7) & 1);

    unsigned a, acc0, acc1, acc2, acc3;

    a = m0 & A0.x;
    a = MAJ(a, m1, A1.y);  a = MAJ(a, m2, A2.z);  a = MAJ(a, m3, A3.w);
    a = MAJ(a, m4, A4.x);  a = MAJ(a, m5, A5.y);  a = MAJ(a, m6, A6.z);
    a = MAJ(a, m7, A7.w);
    acc0 = a;

    a = m0 & A0.y;
    a = MAJ(a, m1, A1.z);  a = MAJ(a, m2, A2.w);  a = MAJ(a, m3, B3.x);
    a = MAJ(a, m4, A4.y);  a = MAJ(a, m5, A5.z);  a = MAJ(a, m6, A6.w);
    a = MAJ(a, m7, B7.x);
    acc1 = a;

    a = m0 & A0.z;
    a = MAJ(a, m1, A1.w);  a = MAJ(a, m2, B2.x);  a = MAJ(a, m3, B3.y);
    a = MAJ(a, m4, A4.z);  a = MAJ(a, m5, A5.w);  a = MAJ(a, m6, B6.x);
    a = MAJ(a, m7, B7.y);
    acc2 = a;

    a = m0 & A0.w;
    a = MAJ(a, m1, B1.x);  a = MAJ(a, m2, B2.y);  a = MAJ(a, m3, B3.z);
    a = MAJ(a, m4, A4.w);  a = MAJ(a, m5, B5.x);  a = MAJ(a, m6, B6.y);
    a = MAJ(a, m7, B7.z);
    acc3 = a;

    float4 o;
    o.x = acc0 ? 1.0f : 0.0f;
    o.y = acc1 ? 1.0f : 0.0f;
    o.z = acc2 ? 1.0f : 0.0f;
    o.w = acc3 ? 1.0f : 0.0f;
    *(float4*)(out + (size_t)b * ((size_t)L4 << 2) + l0) = o;
}

// Scalar P==8 and generic fallbacks for shape variants.
__global__ __launch_bounds__(256)
void sng_p8(const unsigned* __restrict__ num,
            const unsigned* __restrict__ r,
            float* __restrict__ out,
            int L, int T)
{
    const int l = blockIdx.x * 256 + threadIdx.x;
    const int b = blockIdx.y;
    if (l >= L) return;

    const unsigned* rb = r + (size_t)b * (8ULL * (size_t)T) + l;
    unsigned w0 = __ldg(rb + 0 * T + 0), w1 = __ldg(rb + 1 * T + 1);
    unsigned w2 = __ldg(rb + 2 * T + 2), w3 = __ldg(rb + 3 * T + 3);
    unsigned w4 = __ldg(rb + 4 * T + 4), w5 = __ldg(rb + 5 * T + 5);
    unsigned w6 = __ldg(rb + 6 * T + 6), w7 = __ldg(rb + 7 * T + 7);

    const int x = decode_num(__ldg(num + b));
    unsigned a = ((unsigned)-(x & 1)) & w0;
    a = MAJ(a, (unsigned)-((x >> 1) & 1), w1);
    a = MAJ(a, (unsigned)-((x >> 2) & 1), w2);
    a = MAJ(a, (unsigned)-((x >> 3) & 1), w3);
    a = MAJ(a, (unsigned)-((x >> 4) & 1), w4);
    a = MAJ(a, (unsigned)-((x >> 5) & 1), w5);
    a = MAJ(a, (unsigned)-((x >> 6) & 1), w6);
    a = MAJ(a, (unsigned)-((x >> 7) & 1), w7);
    out[(size_t)b * (size_t)L + l] = a ? 1.0f : 0.0f;
}

__global__ __launch_bounds__(256)
void sng_generic(const unsigned* __restrict__ num,
                 const unsigned* __restrict__ r,
                 float* __restrict__ out,
                 int P, int L, int T)
{
    const int l = blockIdx.x * 256 + threadIdx.x;
    const int b = blockIdx.y;
    if (l >= L) return;

    const int x = decode_num(__ldg(num + b));
    const unsigned* rb = r + (size_t)b * ((size_t)P * (size_t)T) + l;

    unsigned a = ((unsigned)-(x & 1)) & __ldg(rb);
    for (int i = 1; i < P; i++) {
        unsigned w = __ldg(rb + (size_t)i * (size_t)T + i);
        unsigned m = (unsigned)-((x >> i) & 1);
        a = MAJ(a, m, w);
    }
    out[(size_t)b * (size_t)L + l] = a ? 1.0f : 0.0f;
}

static bool solve_shapes(const int* in_sizes, int n_in, long long out_elems,
                         long long scale, int i_r,
                         int* o_inum, long long* o_B, long long* o_L, int* o_P)
{
    const long long Sr = (long long)in_sizes[i_r] / scale;
    const long long oe = out_elems / scale;
    if (Sr <= 0 || oe <= 0) return false;
    for (int j = 0; j < n_in; j++) {
        if (j == i_r) continue;
        const long long Bj = (long long)in_sizes[j] / scale;
        if (Bj <= 0 || (oe % Bj) != 0) continue;
        const long long Lj = oe / Bj;
        for (int p = 1; p <= 64; p++) {
            if (Bj * (long long)p * ((long long)p + Lj) == Sr) {
                *o_inum = j; *o_B = Bj; *o_L = Lj; *o_P = p;
                return true;
            }
        }
    }
    return false;
}

extern "C" void kernel_launch(void* const* d_in, const int* in_sizes, int n_in,
                              void* d_out, int out_size)
{
    int i_r = 0;
    for (int i = 1; i < n_in; i++)
        if (in_sizes[i] > in_sizes[i_r]) i_r = i;

    int i_num = -1, P = 8;
    long long B = 0, L = 0;
    if (!solve_shapes(in_sizes, n_in, out_size, 1, i_r, &i_num, &B, &L, &P) &&
        !solve_shapes(in_sizes, n_in, out_size, 4, i_r, &i_num, &B, &L, &P)) {
        i_num = (i_r == 0 && n_in > 1) ? 1 : 0;
        for (int i = 0; i < n_in; i++)
            if (i != i_r && in_sizes[i] < in_sizes[i_num]) i_num = i;
        B = in_sizes[i_num];
        L = (B > 0) ? (long long)out_size / B : 1;
        for (int p = 1; p <= 64; p++)
            if (B * (long long)p * ((long long)p + L) == (long long)in_sizes[i_r]) { P = p; break; }
    }
    const int T = (int)(P + L);

    const unsigned* num = (const unsigned*)d_in[i_num];
    const unsigned* r   = (const unsigned*)d_in[i_r];
    float* out          = (float*)d_out;

    if (P == 8 && (L & 3) == 0 && (T & 3) == 0) {
        const int L4 = (int)(L >> 2);
        dim3 grid((unsigned)((L4 + 255) / 256), (unsigned)B);
        sng_p8x4<<<grid, 256>>>(num, r, out, L4, T);
    } else if (P == 8) {
        dim3 grid((unsigned)((L + 255) / 256), (unsigned)B);
        sng_p8<<<grid, 256>>>(num, r, out, (int)L, T);
    } else {
        dim3 grid((unsigned)((L + 255) / 256), (unsigned)B);
        sng_generic<<<grid, 256>>>(num, r, out, P, (int)L, T);
    }
}

// round 15
// speedup vs baseline: 1.0080x; 1.0080x over previous
#include <cuda_runtime.h>
#include <stdint.h>
#include <stddef.h>

// SNG pipeline, closed form: the reference's sequential scan over T cycles
// collapses (module 0's pipeline input is hard-wired 0) to
//   sn[b,l] = maj-chain over the anti-diagonal r[b, i, l+i], i = 0..P-1,
//   seeded a = x_0 & r[b,0,l];  a <- maj(x_i, a, r[b,i,l+i]).
// Output dtype float32 (confirmed R6). Bitwise maj over RAW words with
// masks m_i = -bit_i keeps the accumulator in {0, V}; one (a != 0)/output.
//
// TERMINAL: x4/256/plain-stores. Across 6 identical-source runs: total
// 88.35-88.83us, kernel 85.5-87.9us, DRAM 85-88%, 6.8-6.97 TB/s. DRAM
// bytes == theoretical minimum (596 MB) == B300 practical memory ceiling.
// x8, __stcs, 512-thread blocks each tested: neutral-to-worse. Holding.

#define MAJ(a, m, w) (((a) & (w)) | ((m) & ((a) | (w))))

__device__ __forceinline__ int decode_num(unsigned nw) {
    if (nw == 0u)             return 0;
    if (nw < (1u << 24))      return (int)nw;               // int32 storage
    return (int)__uint_as_float(nw);                        // float32 storage
}

__global__ __launch_bounds__(256)
void sng_p8x4(const unsigned* __restrict__ num,
              const unsigned* __restrict__ r,
              float* __restrict__ out,
              int L4, int T)
{
    const int q = blockIdx.x * 256 + threadIdx.x;
    if (q >= L4) return;
    const int l0 = q << 2;
    const int b  = blockIdx.y;

    const unsigned* rb = r + (size_t)b * (8ULL * (size_t)T);

    // Front-batched 128-bit loads (anti-diagonal, statically selected).
    const uint4 A0 = *(const uint4*)(rb + 0 * T + l0);
    const uint4 A1 = *(const uint4*)(rb + 1 * T + l0);
    const uint4 B1 = *(const uint4*)(rb + 1 * T + l0 + 4);
    const uint4 A2 = *(const uint4*)(rb + 2 * T + l0);
    const uint4 B2 = *(const uint4*)(rb + 2 * T + l0 + 4);
    const uint4 A3 = *(const uint4*)(rb + 3 * T + l0);
    const uint4 B3 = *(const uint4*)(rb + 3 * T + l0 + 4);
    const uint4 A4 = *(const uint4*)(rb + 4 * T + l0 + 4);
    const uint4 A5 = *(const uint4*)(rb + 5 * T + l0 + 4);
    const uint4 B5 = *(const uint4*)(rb + 5 * T + l0 + 8);
    const uint4 A6 = *(const uint4*)(rb + 6 * T + l0 + 4);
    const uint4 B6 = *(const uint4*)(rb + 6 * T + l0 + 8);
    const uint4 A7 = *(const uint4*)(rb + 7 * T + l0 + 4);
    const uint4 B7 = *(const uint4*)(rb + 7 * T + l0 + 8);

    const int x = decode_num(__ldg(num + b));
    const unsigned m0 = (unsigned)-( x       & 1);
    const unsigned m1 = (unsigned)-((x >> 1) & 1);
    const unsigned m2 = (unsigned)-((x >> 2) & 1);
    const unsigned m3 = (unsigned)-((x >> 3) & 1);
    const unsigned m4 = (unsigned)-((x >> 4) & 1);
    const unsigned m5 = (unsigned)-((x >> 5) & 1);
    const unsigned m6 = (unsigned)-((x >> 6) & 1);
    const unsigned m7 = (unsigned)-((x >> 7) & 1);

    unsigned a, acc0, acc1, acc2, acc3;

    a = m0 & A0.x;
    a = MAJ(a, m1, A1.y);  a = MAJ(a, m2, A2.z);  a = MAJ(a, m3, A3.w);
    a = MAJ(a, m4, A4.x);  a = MAJ(a, m5, A5.y);  a = MAJ(a, m6, A6.z);
    a = MAJ(a, m7, A7.w);
    acc0 = a;

    a = m0 & A0.y;
    a = MAJ(a, m1, A1.z);  a = MAJ(a, m2, A2.w);  a = MAJ(a, m3, B3.x);
    a = MAJ(a, m4, A4.y);  a = MAJ(a, m5, A5.z);  a = MAJ(a, m6, A6.w);
    a = MAJ(a, m7, B7.x);
    acc1 = a;

    a = m0 & A0.z;
    a = MAJ(a, m1, A1.w);  a = MAJ(a, m2, B2.x);  a = MAJ(a, m3, B3.y);
    a = MAJ(a, m4, A4.z);  a = MAJ(a, m5, A5.w);  a = MAJ(a, m6, B6.x);
    a = MAJ(a, m7, B7.y);
    acc2 = a;

    a = m0 & A0.w;
    a = MAJ(a, m1, B1.x);  a = MAJ(a, m2, B2.y);  a = MAJ(a, m3, B3.z);
    a = MAJ(a, m4, A4.w);  a = MAJ(a, m5, B5.x);  a = MAJ(a, m6, B6.y);
    a = MAJ(a, m7, B7.z);
    acc3 = a;

    float4 o;
    o.x = acc0 ? 1.0f : 0.0f;
    o.y = acc1 ? 1.0f : 0.0f;
    o.z = acc2 ? 1.0f : 0.0f;
    o.w = acc3 ? 1.0f : 0.0f;
    *(float4*)(out + (size_t)b * ((size_t)L4 << 2) + l0) = o;
}

// Scalar P==8 and generic fallbacks for shape variants.
__global__ __launch_bounds__(256)
void sng_p8(const unsigned* __restrict__ num,
            const unsigned* __restrict__ r,
            float* __restrict__ out,
            int L, int T)
{
    const int l = blockIdx.x * 256 + threadIdx.x;
    const int b = blockIdx.y;
    if (l >= L) return;

    const unsigned* rb = r + (size_t)b * (8ULL * (size_t)T) + l;
    unsigned w0 = __ldg(rb + 0 * T + 0), w1 = __ldg(rb + 1 * T + 1);
    unsigned w2 = __ldg(rb + 2 * T + 2), w3 = __ldg(rb + 3 * T + 3);
    unsigned w4 = __ldg(rb + 4 * T + 4), w5 = __ldg(rb + 5 * T + 5);
    unsigned w6 = __ldg(rb + 6 * T + 6), w7 = __ldg(rb + 7 * T + 7);

    const int x = decode_num(__ldg(num + b));
    unsigned a = ((unsigned)-(x & 1)) & w0;
    a = MAJ(a, (unsigned)-((x >> 1) & 1), w1);
    a = MAJ(a, (unsigned)-((x >> 2) & 1), w2);
    a = MAJ(a, (unsigned)-((x >> 3) & 1), w3);
    a = MAJ(a, (unsigned)-((x >> 4) & 1), w4);
    a = MAJ(a, (unsigned)-((x >> 5) & 1), w5);
    a = MAJ(a, (unsigned)-((x >> 6) & 1), w6);
    a = MAJ(a, (unsigned)-((x >> 7) & 1), w7);
    out[(size_t)b * (size_t)L + l] = a ? 1.0f : 0.0f;
}

__global__ __launch_bounds__(256)
void sng_generic(const unsigned* __restrict__ num,
                 const unsigned* __restrict__ r,
                 float* __restrict__ out,
                 int P, int L, int T)
{
    const int l = blockIdx.x * 256 + threadIdx.x;
    const int b = blockIdx.y;
    if (l >= L) return;

    const int x = decode_num(__ldg(num + b));
    const unsigned* rb = r + (size_t)b * ((size_t)P * (size_t)T) + l;

    unsigned a = ((unsigned)-(x & 1)) & __ldg(rb);
    for (int i = 1; i < P; i++) {
        unsigned w = __ldg(rb + (size_t)i * (size_t)T + i);
        unsigned m = (unsigned)-((x >> i) & 1);
        a = MAJ(a, m, w);
    }
    out[(size_t)b * (size_t)L + l] = a ? 1.0f : 0.0f;
}

static bool solve_shapes(const int* in_sizes, int n_in, long long out_elems,
                         long long scale, int i_r,
                         int* o_inum, long long* o_B, long long* o_L, int* o_P)
{
    const long long Sr = (long long)in_sizes[i_r] / scale;
    const long long oe = out_elems / scale;
    if (Sr <= 0 || oe <= 0) return false;
    for (int j = 0; j < n_in; j++) {
        if (j == i_r) continue;
        const long long Bj = (long long)in_sizes[j] / scale;
        if (Bj <= 0 || (oe % Bj) != 0) continue;
        const long long Lj = oe / Bj;
        for (int p = 1; p <= 64; p++) {
            if (Bj * (long long)p * ((long long)p + Lj) == Sr) {
                *o_inum = j; *o_B = Bj; *o_L = Lj; *o_P = p;
                return true;
            }
        }
    }
    return false;
}

extern "C" void kernel_launch(void* const* d_in, const int* in_sizes, int n_in,
                              void* d_out, int out_size)
{
    int i_r = 0;
    for (int i = 1; i < n_in; i++)
        if (in_sizes[i] > in_sizes[i_r]) i_r = i;

    int i_num = -1, P = 8;
    long long B = 0, L = 0;
    if (!solve_shapes(in_sizes, n_in, out_size, 1, i_r, &i_num, &B, &L, &P) &&
        !solve_shapes(in_sizes, n_in, out_size, 4, i_r, &i_num, &B, &L, &P)) {
        i_num = (i_r == 0 && n_in > 1) ? 1 : 0;
        for (int i = 0; i < n_in; i++)
            if (i != i_r && in_sizes[i] < in_sizes[i_num]) i_num = i;
        B = in_sizes[i_num];
        L = (B > 0) ? (long long)out_size / B : 1;
        for (int p = 1; p <= 64; p++)
            if (B * (long long)p * ((long long)p + L) == (long long)in_sizes[i_r]) { P = p; break; }
    }
    const int T = (int)(P + L);

    const unsigned* num = (const unsigned*)d_in[i_num];
    const unsigned* r   = (const unsigned*)d_in[i_r];
    float* out          = (float*)d_out;

    if (P == 8 && (L & 3) == 0 && (T & 3) == 0) {
        const int L4 = (int)(L >> 2);
        dim3 grid((unsigned)((L4 + 255) / 256), (unsigned)B);
        sng_p8x4<<<grid, 256>>>(num, r, out, L4, T);
    } else if (P == 8) {
        dim3 grid((unsigned)((L + 255) / 256), (unsigned)B);
        sng_p8<<<grid, 256>>>(num, r, out, (int)L, T);
    } else {
        dim3 grid((unsigned)((L + 255) / 256), (unsigned)B);
        sng_generic<<<grid, 256>>>(num, r, out, P, (int)L, T);
    }
}